// round 1
// baseline (speedup 1.0000x reference)
#include <cuda_runtime.h>
#include <math.h>

#define Bq    8
#define Cc    384
#define Nn    4096       // H*W = 64*64
#define HEADS 8
#define HD    48

// ---------------- scratch (device globals: allocation-free) ----------------
__device__ float g_xs[Bq*Cc*Nn];
__device__ float g_q [Bq*Cc*Nn];
__device__ float g_k [Bq*Cc*Nn];
__device__ float g_v [Bq*Cc*Nn];
__device__ float g_a [Bq*Cc*Nn];
__device__ float g_kv[Bq*HEADS*HD*HD];
__device__ float g_s [4*Cc];
__device__ float g_t [4*Cc];

__device__ __forceinline__ float spikef(float x) {
    // round(clip(x,0,4))/4 ; rintf = round-half-to-even, matches jnp.round
    return rintf(fminf(fmaxf(x, 0.0f), 4.0f)) * 0.25f;
}

// ---------------- BN param prep: s = gamma/sqrt(var+eps), t = beta - mean*s
__global__ void prep_params(const float* __restrict__ gamma,
                            const float* __restrict__ beta,
                            const float* __restrict__ mean,
                            const float* __restrict__ var,
                            float* __restrict__ s, float* __restrict__ t) {
    int i = threadIdx.x;
    if (i < Cc) {
        float sv = gamma[i] / sqrtf(var[i] + 1e-5f);
        s[i] = sv;
        t[i] = beta[i] - mean[i] * sv;
    }
}

// ---------------- xs = spike(x), vectorized ----------------
__global__ void spike_x_kernel(const float* __restrict__ x, float* __restrict__ y, int n4) {
    int i = blockIdx.x * blockDim.x + threadIdx.x;
    if (i < n4) {
        float4 v = reinterpret_cast<const float4*>(x)[i];
        v.x = spikef(v.x); v.y = spikef(v.y); v.z = spikef(v.z); v.w = spikef(v.w);
        reinterpret_cast<float4*>(y)[i] = v;
    }
}

// ---------------- SGEMM: Y[b] = W @ X[b], then y*s[m]+t[m], optional spike --
// W: [Cc x Cc] row-major. X,Y: [B][Cc][Nn]. Tile 128x128x16, 8x8 per thread.
__global__ __launch_bounds__(256, 2)
void sgemm_bn(const float* __restrict__ W, const float* __restrict__ X,
              float* __restrict__ Y, const float* __restrict__ s,
              const float* __restrict__ t, int doSpike)
{
    const int b  = blockIdx.z;
    const int m0 = blockIdx.y * 128;
    const int n0 = blockIdx.x * 128;
    const float* Xb = X + (size_t)b * (Cc * Nn);
    float*       Yb = Y + (size_t)b * (Cc * Nn);

    __shared__ float As[16][128];   // [k][m]
    __shared__ float Bs[16][128];   // [k][n]

    const int tid = threadIdx.x;      // 0..255
    const int tx  = tid & 15;         // n-group
    const int ty  = tid >> 4;         // m-group

    // W-tile load mapping: 128 rows x 4 float4, 2 float4 per thread
    const int wr = tid >> 1;
    const int wc = (tid & 1) * 2;

    float acc[8][8];
    #pragma unroll
    for (int i = 0; i < 8; ++i)
        #pragma unroll
        for (int j = 0; j < 8; ++j) acc[i][j] = 0.0f;

    for (int k0 = 0; k0 < Cc; k0 += 16) {
        #pragma unroll
        for (int i = 0; i < 2; ++i) {
            float4 wv = *reinterpret_cast<const float4*>(
                &W[(size_t)(m0 + wr) * Cc + k0 + (wc + i) * 4]);
            As[(wc + i) * 4 + 0][wr] = wv.x;
            As[(wc + i) * 4 + 1][wr] = wv.y;
            As[(wc + i) * 4 + 2][wr] = wv.z;
            As[(wc + i) * 4 + 3][wr] = wv.w;
        }
        #pragma unroll
        for (int i = 0; i < 2; ++i) {
            float4 xv = *reinterpret_cast<const float4*>(
                &Xb[(size_t)(k0 + ty) * Nn + n0 + (tx + 16 * i) * 4]);
            *reinterpret_cast<float4*>(&Bs[ty][(tx + 16 * i) * 4]) = xv;
        }
        __syncthreads();

        #pragma unroll
        for (int kk = 0; kk < 16; ++kk) {
            float ra[8], rb[8];
            *reinterpret_cast<float4*>(&ra[0]) = *reinterpret_cast<float4*>(&As[kk][ty * 8]);
            *reinterpret_cast<float4*>(&ra[4]) = *reinterpret_cast<float4*>(&As[kk][ty * 8 + 4]);
            *reinterpret_cast<float4*>(&rb[0]) = *reinterpret_cast<float4*>(&Bs[kk][tx * 8]);
            *reinterpret_cast<float4*>(&rb[4]) = *reinterpret_cast<float4*>(&Bs[kk][tx * 8 + 4]);
            #pragma unroll
            for (int i = 0; i < 8; ++i)
                #pragma unroll
                for (int j = 0; j < 8; ++j)
                    acc[i][j] = fmaf(ra[i], rb[j], acc[i][j]);
        }
        __syncthreads();
    }

    #pragma unroll
    for (int i = 0; i < 8; ++i) {
        const int m = m0 + ty * 8 + i;
        const float sv = s[m], tv = t[m];
        float* yp = &Yb[(size_t)m * Nn + n0 + tx * 8];
        #pragma unroll
        for (int j4 = 0; j4 < 2; ++j4) {
            float4 o;
            o.x = acc[i][j4 * 4 + 0] * sv + tv;
            o.y = acc[i][j4 * 4 + 1] * sv + tv;
            o.z = acc[i][j4 * 4 + 2] * sv + tv;
            o.w = acc[i][j4 * 4 + 3] * sv + tv;
            if (doSpike) {
                o.x = spikef(o.x); o.y = spikef(o.y);
                o.z = spikef(o.z); o.w = spikef(o.w);
            }
            *reinterpret_cast<float4*>(&yp[j4 * 4]) = o;
        }
    }
}

// ---------------- kv zero ----------------
__global__ void zero_kv_kernel() {
    int i = blockIdx.x * blockDim.x + threadIdx.x;
    if (i < Bq * HEADS * HD * HD) g_kv[i] = 0.0f;
}

// ---------------- kv[b,h,d,e] += sum_n k[b,h*48+d,n] * v[b,h*48+e,n] --------
// Split N into 8 chunks; fp32 atomicAdd is EXACT here (sums are multiples of
// 1/16 bounded by 2^16 in those units -> every partial is exactly representable).
__global__ __launch_bounds__(256)
void kv_kernel(const float* __restrict__ k, const float* __restrict__ v) {
    const int chunk = blockIdx.x;          // 0..7 (512 n each)
    const int h = blockIdx.y, b = blockIdx.z;
    const int n0 = chunk * 512;
    const float* kp = k + ((size_t)b * Cc + h * HD) * Nn;
    const float* vp = v + ((size_t)b * Cc + h * HD) * Nn;

    __shared__ float ks[HD][65];
    __shared__ float vs[HD][65];

    const int tid = threadIdx.x;
    const int te = tid & 15;    // e-group (3 e's)
    const int td = tid >> 4;    // d-group (3 d's)

    float acc[3][3] = {};

    for (int nt = 0; nt < 512; nt += 64) {
        for (int i = tid; i < HD * 64; i += 256) {
            int r = i >> 6, c = i & 63;
            ks[r][c] = kp[(size_t)r * Nn + n0 + nt + c];
            vs[r][c] = vp[(size_t)r * Nn + n0 + nt + c];
        }
        __syncthreads();
        #pragma unroll 4
        for (int n = 0; n < 64; ++n) {
            float kd[3], ve[3];
            #pragma unroll
            for (int i = 0; i < 3; ++i) kd[i] = ks[td * 3 + i][n];
            #pragma unroll
            for (int i = 0; i < 3; ++i) ve[i] = vs[te * 3 + i][n];
            #pragma unroll
            for (int i = 0; i < 3; ++i)
                #pragma unroll
                for (int j = 0; j < 3; ++j)
                    acc[i][j] = fmaf(kd[i], ve[j], acc[i][j]);
        }
        __syncthreads();
    }

    float* kvp = g_kv + (size_t)(b * HEADS + h) * HD * HD;
    #pragma unroll
    for (int i = 0; i < 3; ++i)
        #pragma unroll
        for (int j = 0; j < 3; ++j)
            atomicAdd(&kvp[(td * 3 + i) * HD + te * 3 + j], acc[i][j]);
}

// ---------------- a[b,h*48+e,n] = spike( (sum_d q[b,h*48+d,n]*kv[d,e]) * m ) -
__global__ __launch_bounds__(256)
void attn_kernel(const float* __restrict__ q, float* __restrict__ a) {
    const int n = blockIdx.x * 256 + threadIdx.x;
    const int h = blockIdx.y, b = blockIdx.z;

    __shared__ float4 kvs[HD][12];
    const float* kvp = g_kv + (size_t)(b * HEADS + h) * HD * HD;
    for (int i = threadIdx.x; i < HD * 12; i += 256)
        reinterpret_cast<float4*>(kvs)[i] = reinterpret_cast<const float4*>(kvp)[i];
    __syncthreads();

    const float* qp = q + ((size_t)b * Cc + h * HD) * Nn + n;
    float qr[HD];
    #pragma unroll
    for (int d = 0; d < HD; ++d) qr[d] = qp[(size_t)d * Nn];

    float* ap = a + ((size_t)b * Cc + h * HD) * Nn + n;
    const float mult = 0.28867513459481287f;   // 2 * 48^-0.5

    #pragma unroll
    for (int e4 = 0; e4 < 12; ++e4) {
        float4 acc = make_float4(0.f, 0.f, 0.f, 0.f);
        #pragma unroll
        for (int d = 0; d < HD; ++d) {
            float4 kvv = kvs[d][e4];
            float qd = qr[d];
            acc.x = fmaf(qd, kvv.x, acc.x);
            acc.y = fmaf(qd, kvv.y, acc.y);
            acc.z = fmaf(qd, kvv.z, acc.z);
            acc.w = fmaf(qd, kvv.w, acc.w);
        }
        ap[(size_t)(e4 * 4 + 0) * Nn] = spikef(acc.x * mult);
        ap[(size_t)(e4 * 4 + 1) * Nn] = spikef(acc.y * mult);
        ap[(size_t)(e4 * 4 + 2) * Nn] = spikef(acc.z * mult);
        ap[(size_t)(e4 * 4 + 3) * Nn] = spikef(acc.w * mult);
    }
}

// ---------------- launch ----------------
extern "C" void kernel_launch(void* const* d_in, const int* in_sizes, int n_in,
                              void* d_out, int out_size) {
    const float* x = (const float*)d_in[0];
    // d_in: 0=x, then per p in {q,k,v,p}: w, gamma, beta, mean, var
    float *xs, *qb, *kb, *vb, *ab, *sarr, *tarr;
    cudaGetSymbolAddress((void**)&xs,   g_xs);
    cudaGetSymbolAddress((void**)&qb,   g_q);
    cudaGetSymbolAddress((void**)&kb,   g_k);
    cudaGetSymbolAddress((void**)&vb,   g_v);
    cudaGetSymbolAddress((void**)&ab,   g_a);
    cudaGetSymbolAddress((void**)&sarr, g_s);
    cudaGetSymbolAddress((void**)&tarr, g_t);

    for (int p = 0; p < 4; ++p) {
        prep_params<<<1, 384>>>((const float*)d_in[2 + p * 5],
                                (const float*)d_in[3 + p * 5],
                                (const float*)d_in[4 + p * 5],
                                (const float*)d_in[5 + p * 5],
                                sarr + p * Cc, tarr + p * Cc);
    }

    const int n4 = Bq * Cc * Nn / 4;
    spike_x_kernel<<<(n4 + 255) / 256, 256>>>(x, xs, n4);

    dim3 gg(Nn / 128, Cc / 128, Bq);
    sgemm_bn<<<gg, 256>>>((const float*)d_in[1],  xs, qb, sarr + 0 * Cc, tarr + 0 * Cc, 1);
    sgemm_bn<<<gg, 256>>>((const float*)d_in[6],  xs, kb, sarr + 1 * Cc, tarr + 1 * Cc, 1);
    sgemm_bn<<<gg, 256>>>((const float*)d_in[11], xs, vb, sarr + 2 * Cc, tarr + 2 * Cc, 1);

    zero_kv_kernel<<<(Bq * HEADS * HD * HD + 255) / 256, 256>>>();
    kv_kernel<<<dim3(8, HEADS, Bq), 256>>>(kb, vb);
    attn_kernel<<<dim3(Nn / 256, HEADS, Bq), 256>>>(qb, ab);

    sgemm_bn<<<gg, 256>>>((const float*)d_in[16], ab, (float*)d_out,
                          sarr + 3 * Cc, tarr + 3 * Cc, 0);
}

// round 3
// speedup vs baseline: 2.8778x; 2.8778x over previous
#include <cuda_runtime.h>
#include <cuda_bf16.h>
#include <math.h>
#include <stdint.h>

#define Bq    8
#define Cc    384
#define Nn    4096
#define HEADS 8
#define HD    48

// ---------------- scratch (device globals) ----------------
__device__ __nv_bfloat16 g_xs[(size_t)Bq*Cc*Nn];   // spike(x)  [b][c][n]
__device__ __nv_bfloat16 g_q [(size_t)Bq*Cc*Nn];
__device__ __nv_bfloat16 g_k [(size_t)Bq*Cc*Nn];
__device__ __nv_bfloat16 g_v [(size_t)Bq*Cc*Nn];
__device__ __nv_bfloat16 g_a [(size_t)Bq*Cc*Nn];
__device__ __nv_bfloat16 g_whi[4*Cc*Cc];
__device__ __nv_bfloat16 g_wlo[4*Cc*Cc];
__device__ float g_kv[Bq*HEADS*HD*HD];
__device__ float g_s [4*Cc];
__device__ float g_t [4*Cc];

__device__ __forceinline__ float spikef(float x) {
    return rintf(fminf(fmaxf(x, 0.0f), 4.0f)) * 0.25f;   // round-half-even = jnp.round
}

// ---------------- PTX helpers (sm_80-era ISA only: compiles on plain sm_103) --
__device__ __forceinline__ uint32_t smem_u32(const void* p) {
    uint32_t a;
    asm("{ .reg .u64 t; cvta.to.shared.u64 t, %1; cvt.u32.u64 %0, t; }" : "=r"(a) : "l"(p));
    return a;
}
__device__ __forceinline__ void cp16(uint32_t s, const void* g) {
    asm volatile("cp.async.cg.shared.global [%0], [%1], 16;" :: "r"(s), "l"(g));
}
__device__ __forceinline__ void ldsm4(uint32_t* r, uint32_t a) {
    asm volatile("ldmatrix.sync.aligned.m8n8.x4.shared.b16 {%0,%1,%2,%3}, [%4];"
        : "=r"(r[0]), "=r"(r[1]), "=r"(r[2]), "=r"(r[3]) : "r"(a));
}
__device__ __forceinline__ void ldsm4t(uint32_t* r, uint32_t a) {
    asm volatile("ldmatrix.sync.aligned.m8n8.x4.trans.shared.b16 {%0,%1,%2,%3}, [%4];"
        : "=r"(r[0]), "=r"(r[1]), "=r"(r[2]), "=r"(r[3]) : "r"(a));
}
__device__ __forceinline__ void mma16816(float* d, const uint32_t* a, const uint32_t* b) {
    asm volatile(
        "mma.sync.aligned.m16n8k16.row.col.f32.bf16.bf16.f32 "
        "{%0,%1,%2,%3}, {%4,%5,%6,%7}, {%8,%9}, {%0,%1,%2,%3};"
        : "+f"(d[0]), "+f"(d[1]), "+f"(d[2]), "+f"(d[3])
        : "r"(a[0]), "r"(a[1]), "r"(a[2]), "r"(a[3]), "r"(b[0]), "r"(b[1]));
}

// ---------------- small prep kernels ----------------
__global__ void prep_params(const float* __restrict__ gamma, const float* __restrict__ beta,
                            const float* __restrict__ mean,  const float* __restrict__ var,
                            float* __restrict__ s, float* __restrict__ t) {
    int i = threadIdx.x;
    if (i < Cc) {
        float sv = gamma[i] / sqrtf(var[i] + 1e-5f);
        s[i] = sv; t[i] = beta[i] - mean[i] * sv;
    }
}
__global__ void split_w(const float* __restrict__ w, __nv_bfloat16* __restrict__ hi,
                        __nv_bfloat16* __restrict__ lo) {
    int i = blockIdx.x * 256 + threadIdx.x;
    if (i < Cc * Cc) {
        float v = w[i];
        __nv_bfloat16 h = __float2bfloat16(v);
        hi[i] = h;
        lo[i] = __float2bfloat16(v - __bfloat162float(h));
    }
}
__global__ void spike_x_kernel(const float* __restrict__ x, __nv_bfloat16* __restrict__ y, int n4) {
    int i = blockIdx.x * 256 + threadIdx.x;
    if (i < n4) {
        float4 v = reinterpret_cast<const float4*>(x)[i];
        __nv_bfloat162 a = __floats2bfloat162_rn(spikef(v.x), spikef(v.y));
        __nv_bfloat162 b = __floats2bfloat162_rn(spikef(v.z), spikef(v.w));
        uint2 pk;
        pk.x = *reinterpret_cast<uint32_t*>(&a);
        pk.y = *reinterpret_cast<uint32_t*>(&b);
        reinterpret_cast<uint2*>(y)[i] = pk;
    }
}

// ---------------- HMMA GEMM: Y = BN(W @ X) [+spike], W = hi+lo bf16 ---------
// A = W rows (row-major [m][k]); B = X [k][n] (n-contiguous) via ldmatrix.trans.
// Block 128x128x32, 8 warps (2m x 4n), warp tile 64x32, double-buffered cp.async.
#define STG_BYTES 24576   // per stage: A_hi 8K + A_lo 8K + B 8K
#define SMEM_GEMM 49152

__global__ __launch_bounds__(256, 2)
void gemm_hmma(const __nv_bfloat16* __restrict__ Whi, const __nv_bfloat16* __restrict__ Wlo,
               const __nv_bfloat16* __restrict__ X, void* __restrict__ Y,
               const float* __restrict__ sArr, const float* __restrict__ tArr, int mode)
{
    extern __shared__ char smem[];
    const uint32_t sb = smem_u32(smem);
    const int tid = threadIdx.x, lane = tid & 31, wid = tid >> 5;
    const int wm = wid & 1, wn = wid >> 1;
    const int n0 = blockIdx.x * 128, m0 = blockIdx.y * 128, b = blockIdx.z;
    const __nv_bfloat16* Xb = X + (size_t)b * (Cc * Nn);

    float acc[4][4][4];
    #pragma unroll
    for (int t = 0; t < 4; ++t)
        #pragma unroll
        for (int u = 0; u < 4; ++u)
            #pragma unroll
            for (int j = 0; j < 4; ++j) acc[t][u][j] = 0.0f;

    // --- async tile loader: swizzled smem, 16B per cp.async ---
    auto load_chunk = [&](int kc, int stg) {
        uint32_t base = sb + stg * STG_BYTES;
        #pragma unroll
        for (int p = 0; p < 2; ++p) {                       // A hi+lo: 128r x 4 chunks
            int idx = tid + p * 256;
            int row = idx >> 2, c = idx & 3;
            uint32_t so = row * 64 + ((c ^ ((row >> 1) & 3)) << 4);
            const __nv_bfloat16* gp = Whi + (size_t)(m0 + row) * Cc + kc * 32 + c * 8;
            cp16(base + so, gp);
            cp16(base + 8192 + so, Wlo + (size_t)(m0 + row) * Cc + kc * 32 + c * 8);
        }
        #pragma unroll
        for (int p = 0; p < 2; ++p) {                       // B: 32k x 16 chunks
            int idx = tid + p * 256;
            int kr = idx >> 4, c = idx & 15;
            uint32_t so = kr * 256 + (((c & 8) | ((c & 7) ^ (kr & 7))) << 4);
            cp16(base + 16384 + so, Xb + (size_t)(kc * 32 + kr) * Nn + n0 + c * 8);
        }
        asm volatile("cp.async.commit_group;");
    };

    load_chunk(0, 0);

    for (int kc = 0; kc < 12; ++kc) {
        if (kc + 1 < 12) {
            load_chunk(kc + 1, (kc + 1) & 1);
            asm volatile("cp.async.wait_group 1;");
        } else {
            asm volatile("cp.async.wait_group 0;");
        }
        __syncthreads();

        uint32_t base = sb + (kc & 1) * STG_BYTES;
        const int sel = lane >> 3, l7 = lane & 7;

        #pragma unroll
        for (int h = 0; h < 2; ++h) {
            uint32_t ahi[4][4], alo[4][4], bb[2][4];
            #pragma unroll
            for (int t = 0; t < 4; ++t) {
                int row = wm * 64 + t * 16 + (sel & 1) * 8 + l7;
                int kcx = h * 2 + (sel >> 1);
                uint32_t ad = base + row * 64 + ((kcx ^ ((row >> 1) & 3)) << 4);
                ldsm4(ahi[t], ad);
                ldsm4(alo[t], ad + 8192);
            }
            #pragma unroll
            for (int j = 0; j < 2; ++j) {
                int kr = h * 16 + (sel & 1) * 8 + l7;
                int nc = (wn * 32 + j * 16 + (sel >> 1) * 8) >> 3;
                uint32_t bd = base + 16384 + kr * 256 +
                              (((nc & 8) | ((nc & 7) ^ (kr & 7))) << 4);
                ldsm4t(bb[j], bd);
            }
            #pragma unroll
            for (int t = 0; t < 4; ++t)
                #pragma unroll
                for (int u = 0; u < 4; ++u) {
                    const uint32_t* bf = &bb[u >> 1][(u & 1) * 2];
                    mma16816(acc[t][u], ahi[t], bf);
                    mma16816(acc[t][u], alo[t], bf);
                }
        }
        __syncthreads();
    }

    // ---------------- epilogue ----------------
    if (mode == 0) {
        // BN + spike -> bf16 [c][n], restage through padded smem for coalescing
        __nv_bfloat16* sm = reinterpret_cast<__nv_bfloat16*>(smem);
        #pragma unroll
        for (int t = 0; t < 4; ++t) {
            int mrow = wm * 64 + t * 16 + (lane >> 2);
            float s0 = sArr[m0 + mrow],     t0 = tArr[m0 + mrow];
            float s1 = sArr[m0 + mrow + 8], t1 = tArr[m0 + mrow + 8];
            #pragma unroll
            for (int u = 0; u < 4; ++u) {
                int col = wn * 32 + u * 8 + 2 * (lane & 3);
                __nv_bfloat162 p0 = __floats2bfloat162_rn(
                    spikef(acc[t][u][0] * s0 + t0), spikef(acc[t][u][1] * s0 + t0));
                __nv_bfloat162 p1 = __floats2bfloat162_rn(
                    spikef(acc[t][u][2] * s1 + t1), spikef(acc[t][u][3] * s1 + t1));
                *reinterpret_cast<__nv_bfloat162*>(sm + mrow * 136 + col) = p0;
                *reinterpret_cast<__nv_bfloat162*>(sm + (mrow + 8) * 136 + col) = p1;
            }
        }
        __syncthreads();
        __nv_bfloat16* Yb = (__nv_bfloat16*)Y + (size_t)b * (Cc * Nn);
        #pragma unroll
        for (int it = 0; it < 8; ++it) {
            int idx = tid + it * 256;
            int row = idx >> 4, c = idx & 15;
            uint4 u4 = *reinterpret_cast<const uint4*>(sm + row * 136 + c * 8);
            *reinterpret_cast<uint4*>(Yb + (size_t)(m0 + row) * Nn + n0 + c * 8) = u4;
        }
    } else {
        // BN only -> fp32 [c][n] direct (final output); float2 stores = full sectors
        float* Yb = (float*)Y + (size_t)b * (Cc * Nn);
        #pragma unroll
        for (int t = 0; t < 4; ++t) {
            int mrow = wm * 64 + t * 16 + (lane >> 2);
            float s0 = sArr[m0 + mrow],     t0 = tArr[m0 + mrow];
            float s1 = sArr[m0 + mrow + 8], t1 = tArr[m0 + mrow + 8];
            #pragma unroll
            for (int u = 0; u < 4; ++u) {
                int col = n0 + wn * 32 + u * 8 + 2 * (lane & 3);
                float2 p0 = make_float2(acc[t][u][0] * s0 + t0, acc[t][u][1] * s0 + t0);
                float2 p1 = make_float2(acc[t][u][2] * s1 + t1, acc[t][u][3] * s1 + t1);
                *reinterpret_cast<float2*>(Yb + (size_t)(m0 + mrow) * Nn + col) = p0;
                *reinterpret_cast<float2*>(Yb + (size_t)(m0 + mrow + 8) * Nn + col) = p1;
            }
        }
    }
}

// ---------------- kv: kv[b,h,d,e] = sum_n k[d,n]*v[e,n] (exact fp32 atomics) --
__global__ void zero_kv_kernel() {
    int i = blockIdx.x * blockDim.x + threadIdx.x;
    if (i < Bq * HEADS * HD * HD) g_kv[i] = 0.0f;
}
__global__ __launch_bounds__(256)
void kv_kernel() {
    const int chunk = blockIdx.x, h = blockIdx.y, b = blockIdx.z;
    const int n0 = chunk * 512;
    const __nv_bfloat16* kp = g_k + ((size_t)b * Cc + h * HD) * Nn;
    const __nv_bfloat16* vp = g_v + ((size_t)b * Cc + h * HD) * Nn;

    __shared__ float ks[HD][65];
    __shared__ float vs[HD][65];

    const int tid = threadIdx.x;
    const int te = tid & 15, td = tid >> 4;
    float acc[3][3] = {};

    for (int nt = 0; nt < 512; nt += 64) {
        for (int i = tid; i < HD * 64; i += 256) {
            int r = i >> 6, c = i & 63;
            ks[r][c] = __bfloat162float(kp[(size_t)r * Nn + n0 + nt + c]);
            vs[r][c] = __bfloat162float(vp[(size_t)r * Nn + n0 + nt + c]);
        }
        __syncthreads();
        #pragma unroll 4
        for (int n = 0; n < 64; ++n) {
            float kd[3], ve[3];
            #pragma unroll
            for (int i = 0; i < 3; ++i) kd[i] = ks[td * 3 + i][n];
            #pragma unroll
            for (int i = 0; i < 3; ++i) ve[i] = vs[te * 3 + i][n];
            #pragma unroll
            for (int i = 0; i < 3; ++i)
                #pragma unroll
                for (int j = 0; j < 3; ++j)
                    acc[i][j] = fmaf(kd[i], ve[j], acc[i][j]);
        }
        __syncthreads();
    }
    float* kvp = g_kv + (size_t)(b * HEADS + h) * HD * HD;
    #pragma unroll
    for (int i = 0; i < 3; ++i)
        #pragma unroll
        for (int j = 0; j < 3; ++j)
            atomicAdd(&kvp[(td * 3 + i) * HD + te * 3 + j], acc[i][j]);
}

// ---------------- attn: a[h*48+e, n] = spike(mult * sum_d q[d,n]*kv[d,e]) ----
__global__ __launch_bounds__(256)
void attn_kernel() {
    const int n = blockIdx.x * 256 + threadIdx.x;
    const int h = blockIdx.y, b = blockIdx.z;

    __shared__ float4 kv4[HD][12];
    const float* kvp = g_kv + (size_t)(b * HEADS + h) * HD * HD;
    for (int i = threadIdx.x; i < HD * 12; i += 256)
        reinterpret_cast<float4*>(kv4)[i] = reinterpret_cast<const float4*>(kvp)[i];
    __syncthreads();

    const __nv_bfloat16* qp = g_q + ((size_t)b * Cc + h * HD) * Nn + n;
    float qr[HD];
    #pragma unroll
    for (int d = 0; d < HD; ++d) qr[d] = __bfloat162float(qp[(size_t)d * Nn]);

    float4 accv[12];
    #pragma unroll
    for (int e = 0; e < 12; ++e) accv[e] = make_float4(0.f, 0.f, 0.f, 0.f);
    #pragma unroll
    for (int d = 0; d < HD; ++d) {
        float qd = qr[d];
        #pragma unroll
        for (int e = 0; e < 12; ++e) {
            float4 kk = kv4[d][e];
            accv[e].x = fmaf(qd, kk.x, accv[e].x);
            accv[e].y = fmaf(qd, kk.y, accv[e].y);
            accv[e].z = fmaf(qd, kk.z, accv[e].z);
            accv[e].w = fmaf(qd, kk.w, accv[e].w);
        }
    }

    __nv_bfloat16* ap = g_a + ((size_t)b * Cc + h * HD) * Nn + n;
    const float mult = 0.28867513459481287f;   // 2 / sqrt(48)
    #pragma unroll
    for (int e = 0; e < 12; ++e) {
        ap[(size_t)(e * 4 + 0) * Nn] = __float2bfloat16(spikef(accv[e].x * mult));
        ap[(size_t)(e * 4 + 1) * Nn] = __float2bfloat16(spikef(accv[e].y * mult));
        ap[(size_t)(e * 4 + 2) * Nn] = __float2bfloat16(spikef(accv[e].z * mult));
        ap[(size_t)(e * 4 + 3) * Nn] = __float2bfloat16(spikef(accv[e].w * mult));
    }
}

// ---------------- launch ----------------
extern "C" void kernel_launch(void* const* d_in, const int* in_sizes, int n_in,
                              void* d_out, int out_size) {
    const float* x = (const float*)d_in[0];
    __nv_bfloat16 *xs, *qb, *kb, *vb, *ab, *whi, *wlo;
    float *sarr, *tarr;
    cudaGetSymbolAddress((void**)&xs,  g_xs);
    cudaGetSymbolAddress((void**)&qb,  g_q);
    cudaGetSymbolAddress((void**)&kb,  g_k);
    cudaGetSymbolAddress((void**)&vb,  g_v);
    cudaGetSymbolAddress((void**)&ab,  g_a);
    cudaGetSymbolAddress((void**)&whi, g_whi);
    cudaGetSymbolAddress((void**)&wlo, g_wlo);
    cudaGetSymbolAddress((void**)&sarr, g_s);
    cudaGetSymbolAddress((void**)&tarr, g_t);

    cudaFuncSetAttribute(gemm_hmma, cudaFuncAttributeMaxDynamicSharedMemorySize, SMEM_GEMM);

    for (int p = 0; p < 4; ++p) {
        prep_params<<<1, 384>>>((const float*)d_in[2 + p * 5], (const float*)d_in[3 + p * 5],
                                (const float*)d_in[4 + p * 5], (const float*)d_in[5 + p * 5],
                                sarr + p * Cc, tarr + p * Cc);
        split_w<<<(Cc * Cc + 255) / 256, 256>>>((const float*)d_in[1 + p * 5],
                                                whi + p * Cc * Cc, wlo + p * Cc * Cc);
    }

    const int n4 = Bq * Cc * Nn / 4;
    spike_x_kernel<<<(n4 + 255) / 256, 256>>>(x, xs, n4);

    dim3 gg(Nn / 128, Cc / 128, Bq);
    gemm_hmma<<<gg, 256, SMEM_GEMM>>>(whi + 0 * Cc * Cc, wlo + 0 * Cc * Cc, xs, qb,
                                      sarr + 0 * Cc, tarr + 0 * Cc, 0);
    gemm_hmma<<<gg, 256, SMEM_GEMM>>>(whi + 1 * Cc * Cc, wlo + 1 * Cc * Cc, xs, kb,
                                      sarr + 1 * Cc, tarr + 1 * Cc, 0);
    gemm_hmma<<<gg, 256, SMEM_GEMM>>>(whi + 2 * Cc * Cc, wlo + 2 * Cc * Cc, xs, vb,
                                      sarr + 2 * Cc, tarr + 2 * Cc, 0);

    zero_kv_kernel<<<(Bq * HEADS * HD * HD + 255) / 256, 256>>>();
    kv_kernel<<<dim3(8, HEADS, Bq), 256>>>();
    attn_kernel<<<dim3(Nn / 256, HEADS, Bq), 256>>>();

    gemm_hmma<<<gg, 256, SMEM_GEMM>>>(whi + 3 * Cc * Cc, wlo + 3 * Cc * Cc, ab, d_out,
                                      sarr + 3 * Cc, tarr + 3 * Cc, 1);
}